// round 1
// baseline (speedup 1.0000x reference)
#include <cuda_runtime.h>
#include <math.h>

// Problem constants
#define B_   8
#define S_   1024
#define D_   512
#define NH_  8
#define HD_  64
#define MT_  (B_ * S_)      // 8192 rows
#define BH_  (B_ * NH_)     // 64 batch*head

// -------- device scratch (allocation-free: static __device__ globals) --------
__device__ float g_qh[MT_ * D_];
__device__ float g_kh[MT_ * D_];
__device__ float g_vh[MT_ * D_];
__device__ float g_ph[MT_ * D_];
__device__ float g_ctx[MT_ * D_];
__device__ float g_pos[(size_t)BH_ * S_ * S_];   // 256 MB pos-raw scores
__device__ int   g_mask_mode;                    // 0=u8, 1=i32, 2=f32

// ---------------------------------------------------------------------------
// Mask dtype detector: bool isn't in the harness dtype list, so sniff the
// buffer. f32 0/1 pattern, i32 0/1 pattern, else bytes. Deterministic.
// ---------------------------------------------------------------------------
__global__ void detect_mask_kernel(const void* __restrict__ mask) {
    if (threadIdx.x != 0 || blockIdx.x != 0) return;
    const float* f = (const float*)mask;
    const int*   ip = (const int*)mask;
    bool f32ok = true, has1 = false;
    for (int i = 0; i < 1024; i++) {
        float v = f[i];
        if (!(v == 0.0f || v == 1.0f)) { f32ok = false; break; }
        if (v == 1.0f) has1 = true;
    }
    if (f32ok && has1) { g_mask_mode = 2; return; }
    bool i32ok = true;
    for (int i = 0; i < 1024; i++) {
        int v = ip[i];
        if (v != 0 && v != 1) { i32ok = false; break; }
    }
    g_mask_mode = i32ok ? 1 : 0;
}

// ---------------------------------------------------------------------------
// SGEMM (NT): C[m,n] = sum_k A[m,k] * W[n,k] (+ bias[n])
// A: [8192,512] row-major, W: [512,512] row-major. Tile 64x64, BK=16,
// 256 threads, 4x4 per-thread micro-tile.
// ---------------------------------------------------------------------------
__global__ void __launch_bounds__(256)
sgemm_nt_64(const float* __restrict__ A, const float* __restrict__ W,
            const float* __restrict__ bias, float* __restrict__ C)
{
    __shared__ float As[16][64];
    __shared__ float Bs[16][64];
    const int tid = threadIdx.x;
    const int tm = tid >> 4, tn = tid & 15;
    const int m0 = blockIdx.y << 6, n0 = blockIdx.x << 6;
    const int lr = tid >> 2, lc = (tid & 3) << 2;
    float acc[4][4] = {};

    const float* Ap = A + (size_t)(m0 + lr) * D_ + lc;
    const float* Wp = W + (size_t)(n0 + lr) * D_ + lc;

    for (int k0 = 0; k0 < D_; k0 += 16) {
        float4 a = *(const float4*)(Ap + k0);
        float4 b = *(const float4*)(Wp + k0);
        __syncthreads();
        As[lc + 0][lr] = a.x; As[lc + 1][lr] = a.y; As[lc + 2][lr] = a.z; As[lc + 3][lr] = a.w;
        Bs[lc + 0][lr] = b.x; Bs[lc + 1][lr] = b.y; Bs[lc + 2][lr] = b.z; Bs[lc + 3][lr] = b.w;
        __syncthreads();
        #pragma unroll
        for (int kk = 0; kk < 16; kk++) {
            float4 av = *(const float4*)&As[kk][tm << 2];
            float4 bv = *(const float4*)&Bs[kk][tn << 2];
            float ar[4] = {av.x, av.y, av.z, av.w};
            float br[4] = {bv.x, bv.y, bv.z, bv.w};
            #pragma unroll
            for (int i = 0; i < 4; i++)
                #pragma unroll
                for (int j = 0; j < 4; j++)
                    acc[i][j] += ar[i] * br[j];
        }
    }

    float bvreg[4] = {0.f, 0.f, 0.f, 0.f};
    if (bias) {
        #pragma unroll
        for (int j = 0; j < 4; j++) bvreg[j] = bias[n0 + (tn << 2) + j];
    }
    #pragma unroll
    for (int i = 0; i < 4; i++) {
        const int m = m0 + (tm << 2) + i;
        #pragma unroll
        for (int j = 0; j < 4; j++)
            C[(size_t)m * D_ + n0 + (tn << 2) + j] = acc[i][j] + bvreg[j];
    }
}

// ---------------------------------------------------------------------------
// Batched score GEMM per (b,h): S[q,n] = sum_d (qh[q,d]+hbias[d]) * Bmat[n,d]
// MODE 0: write raw pos scores to g_pos.
// MODE 1: content; epilogue fuses relative shift + scale + mask -> attn buf.
//   shift[q,k] = P[q, k-q+S-1]   (k <= q)
//              = 0               (k == q+1)
//              = P[q+1, k-q-2]   (k >  q+1)
// ---------------------------------------------------------------------------
template<int MODE>
__global__ void __launch_bounds__(256)
score_kernel(const float* __restrict__ Bmat, const float* __restrict__ hbias,
             const void* __restrict__ mask, float* __restrict__ outp)
{
    const int bh = blockIdx.z, b = bh >> 3, h = bh & 7;
    const int q0 = blockIdx.y << 6, n0 = blockIdx.x << 6;
    __shared__ float As[16][64];
    __shared__ float Bs[16][64];
    const int tid = threadIdx.x;
    const int tm = tid >> 4, tn = tid & 15;
    const int lr = tid >> 2, lc = (tid & 3) << 2;
    float acc[4][4] = {};

    const float* Ap = g_qh + (size_t)((b << 10) + q0 + lr) * D_ + (h << 6) + lc;
    const float* Bp = Bmat + (size_t)((b << 10) + n0 + lr) * D_ + (h << 6) + lc;
    const float* hb = hbias + (h << 6) + lc;

    #pragma unroll
    for (int k0 = 0; k0 < HD_; k0 += 16) {
        float4 a  = *(const float4*)(Ap + k0);
        float4 bb = *(const float4*)(Bp + k0);
        float4 h4 = *(const float4*)(hb + k0);
        a.x += h4.x; a.y += h4.y; a.z += h4.z; a.w += h4.w;
        __syncthreads();
        As[lc + 0][lr] = a.x;  As[lc + 1][lr] = a.y;  As[lc + 2][lr] = a.z;  As[lc + 3][lr] = a.w;
        Bs[lc + 0][lr] = bb.x; Bs[lc + 1][lr] = bb.y; Bs[lc + 2][lr] = bb.z; Bs[lc + 3][lr] = bb.w;
        __syncthreads();
        #pragma unroll
        for (int kk = 0; kk < 16; kk++) {
            float4 av = *(const float4*)&As[kk][tm << 2];
            float4 bv = *(const float4*)&Bs[kk][tn << 2];
            float ar[4] = {av.x, av.y, av.z, av.w};
            float br[4] = {bv.x, bv.y, bv.z, bv.w};
            #pragma unroll
            for (int i = 0; i < 4; i++)
                #pragma unroll
                for (int j = 0; j < 4; j++)
                    acc[i][j] += ar[i] * br[j];
        }
    }

    if (MODE == 0) {
        float* o = g_pos + (size_t)bh * S_ * S_;
        #pragma unroll
        for (int i = 0; i < 4; i++) {
            const int q = q0 + (tm << 2) + i;
            #pragma unroll
            for (int j = 0; j < 4; j++)
                o[(size_t)q * S_ + n0 + (tn << 2) + j] = acc[i][j];
        }
    } else {
        const int mm = g_mask_mode;
        const float scale = 0.04419417382415922f;  // 1/sqrt(512)
        float* o = outp + (size_t)bh * S_ * S_;
        const float* P = g_pos + (size_t)bh * S_ * S_;
        #pragma unroll
        for (int i = 0; i < 4; i++) {
            const int q = q0 + (tm << 2) + i;
            #pragma unroll
            for (int j = 0; j < 4; j++) {
                const int kcol = n0 + (tn << 2) + j;
                float p;
                if (kcol <= q)          p = P[(size_t)q * S_ + (kcol - q + S_ - 1)];
                else if (kcol == q + 1) p = 0.0f;
                else                    p = P[(size_t)(q + 1) * S_ + (kcol - q - 2)];
                float sc = (acc[i][j] + p) * scale;
                const size_t midx = (size_t)b * S_ * S_ + (size_t)q * S_ + kcol;
                bool msk;
                if (mm == 1)      msk = ((const int*)mask)[midx] != 0;
                else if (mm == 2) msk = ((const float*)mask)[midx] != 0.0f;
                else              msk = ((const unsigned char*)mask)[midx] != 0;
                o[(size_t)q * S_ + kcol] = msk ? -10000.0f : sc;
            }
        }
    }
}

// ---------------------------------------------------------------------------
// Row softmax over S=1024, one 256-thread block per row, in place.
// ---------------------------------------------------------------------------
__global__ void __launch_bounds__(256)
softmax_kernel(float* __restrict__ attn)
{
    const size_t row = blockIdx.x;
    float* p = attn + row * S_;
    const int tid = threadIdx.x;

    float v0 = p[tid], v1 = p[tid + 256], v2 = p[tid + 512], v3 = p[tid + 768];
    float mx = fmaxf(fmaxf(v0, v1), fmaxf(v2, v3));

    __shared__ float red[8];
    #pragma unroll
    for (int o = 16; o > 0; o >>= 1) mx = fmaxf(mx, __shfl_xor_sync(0xffffffffu, mx, o));
    if ((tid & 31) == 0) red[tid >> 5] = mx;
    __syncthreads();
    float m = fmaxf(fmaxf(fmaxf(red[0], red[1]), fmaxf(red[2], red[3])),
                    fmaxf(fmaxf(red[4], red[5]), fmaxf(red[6], red[7])));
    __syncthreads();

    v0 = __expf(v0 - m); v1 = __expf(v1 - m); v2 = __expf(v2 - m); v3 = __expf(v3 - m);
    float s = v0 + v1 + v2 + v3;
    #pragma unroll
    for (int o = 16; o > 0; o >>= 1) s += __shfl_xor_sync(0xffffffffu, s, o);
    if ((tid & 31) == 0) red[tid >> 5] = s;
    __syncthreads();
    float tot = red[0] + red[1] + red[2] + red[3] + red[4] + red[5] + red[6] + red[7];
    float inv = 1.0f / tot;

    p[tid]       = v0 * inv;
    p[tid + 256] = v1 * inv;
    p[tid + 512] = v2 * inv;
    p[tid + 768] = v3 * inv;
}

// ---------------------------------------------------------------------------
// Batched AV GEMM per (b,h): ctx[q, hd] = sum_k attn[q,k] * vh[k, hd]
// M=1024, N=64, K=1024. Tile 64 (q) x 64 (n), BK=16.
// ---------------------------------------------------------------------------
__global__ void __launch_bounds__(256)
av_kernel(const float* __restrict__ attn)
{
    const int bh = blockIdx.z, b = bh >> 3, h = bh & 7;
    const int q0 = blockIdx.y << 6;
    __shared__ float As[16][64];
    __shared__ float Bs[16][64];
    const int tid = threadIdx.x;
    const int tm = tid >> 4, tn = tid & 15;
    const int lr = tid >> 2, lc = (tid & 3) << 2;   // attn tile: row q=lr, k off lc
    const int br = tid >> 4, bc = (tid & 15) << 2;  // vh   tile: k row br, n col bc
    float acc[4][4] = {};

    const float* Ap = attn + (size_t)bh * S_ * S_ + (size_t)(q0 + lr) * S_ + lc;
    const float* Vp = g_vh + (size_t)((b << 10) + br) * D_ + (h << 6) + bc;

    for (int k0 = 0; k0 < S_; k0 += 16) {
        float4 a  = *(const float4*)(Ap + k0);
        float4 vv = *(const float4*)(Vp + (size_t)k0 * D_);
        __syncthreads();
        As[lc + 0][lr] = a.x; As[lc + 1][lr] = a.y; As[lc + 2][lr] = a.z; As[lc + 3][lr] = a.w;
        *(float4*)&Bs[br][bc] = vv;
        __syncthreads();
        #pragma unroll
        for (int kk = 0; kk < 16; kk++) {
            float4 av = *(const float4*)&As[kk][tm << 2];
            float4 bv = *(const float4*)&Bs[kk][tn << 2];
            float ar[4] = {av.x, av.y, av.z, av.w};
            float br2[4] = {bv.x, bv.y, bv.z, bv.w};
            #pragma unroll
            for (int i = 0; i < 4; i++)
                #pragma unroll
                for (int j = 0; j < 4; j++)
                    acc[i][j] += ar[i] * br2[j];
        }
    }

    #pragma unroll
    for (int i = 0; i < 4; i++) {
        const int q = q0 + (tm << 2) + i;
        #pragma unroll
        for (int j = 0; j < 4; j++)
            g_ctx[(size_t)((b << 10) + q) * D_ + (h << 6) + (tn << 2) + j] = acc[i][j];
    }
}

// ---------------------------------------------------------------------------
// kernel_launch: graph-capturable pipeline, default stream, no allocations.
// Output layout: context [8,1024,512] then attn [8,8,1024,1024].
// ---------------------------------------------------------------------------
extern "C" void kernel_launch(void* const* d_in, const int* in_sizes, int n_in,
                              void* d_out, int out_size)
{
    const float* q    = (const float*)d_in[0];
    const float* k    = (const float*)d_in[1];
    const float* v    = (const float*)d_in[2];
    const float* pos  = (const float*)d_in[3];
    const void*  mask = d_in[4];
    const float* Wq   = (const float*)d_in[5];
    const float* bq   = (const float*)d_in[6];
    const float* Wk   = (const float*)d_in[7];
    const float* bk   = (const float*)d_in[8];
    const float* Wv   = (const float*)d_in[9];
    const float* bv   = (const float*)d_in[10];
    const float* Wpos = (const float*)d_in[11];
    const float* Wout = (const float*)d_in[12];
    const float* bout = (const float*)d_in[13];
    const float* u    = (const float*)d_in[14];
    const float* vb   = (const float*)d_in[15];

    float* out  = (float*)d_out;
    float* attn = out + (size_t)MT_ * D_;   // context first, then attn

    float *p_qh, *p_kh, *p_vh, *p_ph, *p_ctx;
    cudaGetSymbolAddress((void**)&p_qh,  g_qh);
    cudaGetSymbolAddress((void**)&p_kh,  g_kh);
    cudaGetSymbolAddress((void**)&p_vh,  g_vh);
    cudaGetSymbolAddress((void**)&p_ph,  g_ph);
    cudaGetSymbolAddress((void**)&p_ctx, g_ctx);

    detect_mask_kernel<<<1, 32>>>(mask);

    // Projections: x @ W^T + b
    dim3 gproj(D_ / 64, MT_ / 64);
    sgemm_nt_64<<<gproj, 256>>>(q,   Wq,   bq,      p_qh);
    sgemm_nt_64<<<gproj, 256>>>(k,   Wk,   bk,      p_kh);
    sgemm_nt_64<<<gproj, 256>>>(v,   Wv,   bv,      p_vh);
    sgemm_nt_64<<<gproj, 256>>>(pos, Wpos, nullptr, p_ph);

    // Raw positional scores: (qh + v_bias) . ph^T  -> g_pos
    dim3 gscore(S_ / 64, S_ / 64, BH_);
    score_kernel<0><<<gscore, 256>>>(p_ph, vb, mask, attn);

    // Content + shift + scale + mask -> pre-softmax scores into attn buffer
    score_kernel<1><<<gscore, 256>>>(p_kh, u, mask, attn);

    // Row softmax (in place)
    softmax_kernel<<<BH_ * S_, 256>>>(attn);

    // context heads = attn @ vh
    dim3 gav(1, S_ / 64, BH_);
    av_kernel<<<gav, 256>>>(attn);

    // Output projection: ctx @ Wout^T + bout -> d_out
    sgemm_nt_64<<<gproj, 256>>>(p_ctx, Wout, bout, out);
}

// round 2
// speedup vs baseline: 1.6345x; 1.6345x over previous
#include <cuda_runtime.h>
#include <math.h>

// Problem constants
#define B_   8
#define S_   1024
#define D_   512
#define NH_  8
#define HD_  64
#define MT_  (B_ * S_)      // 8192 rows
#define BH_  (B_ * NH_)     // 64 batch*head

// -------- device scratch (allocation-free: static __device__ globals) --------
__device__ float g_qh[MT_ * D_];
__device__ float g_kh[MT_ * D_];
__device__ float g_vh[MT_ * D_];
__device__ float g_ph[MT_ * D_];
__device__ float g_ctx[MT_ * D_];
__device__ float g_pos[(size_t)BH_ * S_ * S_];   // 256 MB pos-raw scores
__device__ int   g_mask_mode;                    // 0=u8, 1=i32, 2=f32

// ---------------------------------------------------------------------------
// Mask dtype detector (bool not in harness dtype list; sniff deterministically)
// ---------------------------------------------------------------------------
__global__ void detect_mask_kernel(const void* __restrict__ mask) {
    if (threadIdx.x != 0 || blockIdx.x != 0) return;
    const float* f = (const float*)mask;
    const int*   ip = (const int*)mask;
    bool f32ok = true, has1 = false;
    for (int i = 0; i < 1024; i++) {
        float v = f[i];
        if (!(v == 0.0f || v == 1.0f)) { f32ok = false; break; }
        if (v == 1.0f) has1 = true;
    }
    if (f32ok && has1) { g_mask_mode = 2; return; }
    bool i32ok = true;
    for (int i = 0; i < 1024; i++) {
        int v = ip[i];
        if (v != 0 && v != 1) { i32ok = false; break; }
    }
    g_mask_mode = i32ok ? 1 : 0;
}

// ---------------------------------------------------------------------------
// tf32 helpers
// ---------------------------------------------------------------------------
__device__ __forceinline__ unsigned f2tf(float x) {
    unsigned u;
    asm("cvt.rna.tf32.f32 %0, %1;" : "=r"(u) : "f"(x));
    return u;
}

__device__ __forceinline__ void mma8(float* d, const unsigned* a, const unsigned* b) {
    asm volatile(
        "mma.sync.aligned.m16n8k8.row.col.f32.tf32.tf32.f32 "
        "{%0,%1,%2,%3},{%4,%5,%6,%7},{%8,%9},{%0,%1,%2,%3};"
        : "+f"(d[0]), "+f"(d[1]), "+f"(d[2]), "+f"(d[3])
        : "r"(a[0]), "r"(a[1]), "r"(a[2]), "r"(a[3]), "r"(b[0]), "r"(b[1]));
}

// ---------------------------------------------------------------------------
// NT tf32 GEMM: C[m,n] = sum_k A[m,k] * W[n,k] (+ bias[n])
// A: [M,512] rm, W: [512,512] rm. Block tile 128x64, BK=32, 8 warps (4m x 2n),
// warp tile 32x32 (2x4 m16n8k8 per k-step).
// ---------------------------------------------------------------------------
__global__ void __launch_bounds__(256)
gemm_nt_tf32(const float* __restrict__ A, const float* __restrict__ W,
             const float* __restrict__ bias, float* __restrict__ C)
{
    __shared__ unsigned As[128][36];
    __shared__ unsigned Bs[64][36];
    const int tid  = threadIdx.x;
    const int warp = tid >> 5, lane = tid & 31;
    const int g = lane >> 2, t = lane & 3;
    const int wm = (warp >> 1) << 5, wn = (warp & 1) << 5;
    const int m0 = blockIdx.y << 7, n0 = blockIdx.x << 6;

    const int ar = tid >> 1, ac = (tid & 1) << 4;
    const int br = tid >> 2, bc = (tid & 3) << 3;

    float acc[2][4][4] = {};

    for (int k0 = 0; k0 < D_; k0 += 32) {
        const float* Ap = A + (size_t)(m0 + ar) * D_ + k0 + ac;
        const float* Wp = W + (size_t)(n0 + br) * D_ + k0 + bc;
        float4 a0 = *(const float4*)(Ap + 0);
        float4 a1 = *(const float4*)(Ap + 4);
        float4 a2 = *(const float4*)(Ap + 8);
        float4 a3 = *(const float4*)(Ap + 12);
        float4 b0 = *(const float4*)(Wp + 0);
        float4 b1 = *(const float4*)(Wp + 4);
        __syncthreads();
        *(uint4*)&As[ar][ac + 0]  = make_uint4(f2tf(a0.x), f2tf(a0.y), f2tf(a0.z), f2tf(a0.w));
        *(uint4*)&As[ar][ac + 4]  = make_uint4(f2tf(a1.x), f2tf(a1.y), f2tf(a1.z), f2tf(a1.w));
        *(uint4*)&As[ar][ac + 8]  = make_uint4(f2tf(a2.x), f2tf(a2.y), f2tf(a2.z), f2tf(a2.w));
        *(uint4*)&As[ar][ac + 12] = make_uint4(f2tf(a3.x), f2tf(a3.y), f2tf(a3.z), f2tf(a3.w));
        *(uint4*)&Bs[br][bc + 0]  = make_uint4(f2tf(b0.x), f2tf(b0.y), f2tf(b0.z), f2tf(b0.w));
        *(uint4*)&Bs[br][bc + 4]  = make_uint4(f2tf(b1.x), f2tf(b1.y), f2tf(b1.z), f2tf(b1.w));
        __syncthreads();
        #pragma unroll
        for (int kk = 0; kk < 4; kk++) {
            const int k8 = kk << 3;
            unsigned af[2][4], bf[4][2];
            #pragma unroll
            for (int mt = 0; mt < 2; mt++) {
                const int r = wm + (mt << 4) + g;
                af[mt][0] = As[r][k8 + t];
                af[mt][1] = As[r + 8][k8 + t];
                af[mt][2] = As[r][k8 + t + 4];
                af[mt][3] = As[r + 8][k8 + t + 4];
            }
            #pragma unroll
            for (int nt = 0; nt < 4; nt++) {
                const int r = wn + (nt << 3) + g;
                bf[nt][0] = Bs[r][k8 + t];
                bf[nt][1] = Bs[r][k8 + t + 4];
            }
            #pragma unroll
            for (int mt = 0; mt < 2; mt++)
                #pragma unroll
                for (int nt = 0; nt < 4; nt++)
                    mma8(acc[mt][nt], af[mt], bf[nt]);
        }
    }

    #pragma unroll
    for (int mt = 0; mt < 2; mt++) {
        #pragma unroll
        for (int nt = 0; nt < 4; nt++) {
            const int row = m0 + wm + (mt << 4) + g;
            const int col = n0 + wn + (nt << 3) + (t << 1);
            float bv0 = bias ? bias[col] : 0.0f;
            float bv1 = bias ? bias[col + 1] : 0.0f;
            C[(size_t)row * D_ + col]           = acc[mt][nt][0] + bv0;
            C[(size_t)row * D_ + col + 1]       = acc[mt][nt][1] + bv1;
            C[(size_t)(row + 8) * D_ + col]     = acc[mt][nt][2] + bv0;
            C[(size_t)(row + 8) * D_ + col + 1] = acc[mt][nt][3] + bv1;
        }
    }
}

// ---------------------------------------------------------------------------
// Batched score GEMM per (b,h): S[q,n] = sum_d (qh[q,d]+hbias[d]) * Bmat[n,d]
// Same tile shape as gemm_nt_tf32, K=64.
// MODE 0: write raw pos scores to g_pos.
// MODE 1: content; epilogue fuses relative shift + scale + mask -> attn buf.
//   shift[q,k] = P[q, k-q+S-1] (k<=q) ; 0 (k==q+1) ; P[q+1, k-q-2] (k>q+1)
// ---------------------------------------------------------------------------
template<int MODE>
__global__ void __launch_bounds__(256)
score_tf32(const float* __restrict__ Bmat, const float* __restrict__ hbias,
           const void* __restrict__ mask, float* __restrict__ attnout)
{
    __shared__ unsigned As[128][36];
    __shared__ unsigned Bs[64][36];
    const int bh = blockIdx.z, b = bh >> 3, h = bh & 7;
    const int tid  = threadIdx.x;
    const int warp = tid >> 5, lane = tid & 31;
    const int g = lane >> 2, t = lane & 3;
    const int wm = (warp >> 1) << 5, wn = (warp & 1) << 5;
    const int m0 = blockIdx.y << 7, n0 = blockIdx.x << 6;

    const int ar = tid >> 1, ac = (tid & 1) << 4;
    const int br = tid >> 2, bc = (tid & 3) << 3;

    float acc[2][4][4] = {};

    #pragma unroll
    for (int k0 = 0; k0 < HD_; k0 += 32) {
        const float* Ap = g_qh + (size_t)((b << 10) + m0 + ar) * D_ + (h << 6) + k0 + ac;
        const float* Bp = Bmat + (size_t)((b << 10) + n0 + br) * D_ + (h << 6) + k0 + bc;
        const float* Hp = hbias + (h << 6) + k0 + ac;
        float4 a0 = *(const float4*)(Ap + 0);
        float4 a1 = *(const float4*)(Ap + 4);
        float4 a2 = *(const float4*)(Ap + 8);
        float4 a3 = *(const float4*)(Ap + 12);
        float4 h0 = *(const float4*)(Hp + 0);
        float4 h1 = *(const float4*)(Hp + 4);
        float4 h2 = *(const float4*)(Hp + 8);
        float4 h3 = *(const float4*)(Hp + 12);
        float4 b0 = *(const float4*)(Bp + 0);
        float4 b1 = *(const float4*)(Bp + 4);
        a0.x += h0.x; a0.y += h0.y; a0.z += h0.z; a0.w += h0.w;
        a1.x += h1.x; a1.y += h1.y; a1.z += h1.z; a1.w += h1.w;
        a2.x += h2.x; a2.y += h2.y; a2.z += h2.z; a2.w += h2.w;
        a3.x += h3.x; a3.y += h3.y; a3.z += h3.z; a3.w += h3.w;
        __syncthreads();
        *(uint4*)&As[ar][ac + 0]  = make_uint4(f2tf(a0.x), f2tf(a0.y), f2tf(a0.z), f2tf(a0.w));
        *(uint4*)&As[ar][ac + 4]  = make_uint4(f2tf(a1.x), f2tf(a1.y), f2tf(a1.z), f2tf(a1.w));
        *(uint4*)&As[ar][ac + 8]  = make_uint4(f2tf(a2.x), f2tf(a2.y), f2tf(a2.z), f2tf(a2.w));
        *(uint4*)&As[ar][ac + 12] = make_uint4(f2tf(a3.x), f2tf(a3.y), f2tf(a3.z), f2tf(a3.w));
        *(uint4*)&Bs[br][bc + 0]  = make_uint4(f2tf(b0.x), f2tf(b0.y), f2tf(b0.z), f2tf(b0.w));
        *(uint4*)&Bs[br][bc + 4]  = make_uint4(f2tf(b1.x), f2tf(b1.y), f2tf(b1.z), f2tf(b1.w));
        __syncthreads();
        #pragma unroll
        for (int kk = 0; kk < 4; kk++) {
            const int k8 = kk << 3;
            unsigned af[2][4], bf[4][2];
            #pragma unroll
            for (int mt = 0; mt < 2; mt++) {
                const int r = wm + (mt << 4) + g;
                af[mt][0] = As[r][k8 + t];
                af[mt][1] = As[r + 8][k8 + t];
                af[mt][2] = As[r][k8 + t + 4];
                af[mt][3] = As[r + 8][k8 + t + 4];
            }
            #pragma unroll
            for (int nt = 0; nt < 4; nt++) {
                const int r = wn + (nt << 3) + g;
                bf[nt][0] = Bs[r][k8 + t];
                bf[nt][1] = Bs[r][k8 + t + 4];
            }
            #pragma unroll
            for (int mt = 0; mt < 2; mt++)
                #pragma unroll
                for (int nt = 0; nt < 4; nt++)
                    mma8(acc[mt][nt], af[mt], bf[nt]);
        }
    }

    if (MODE == 0) {
        float* o = g_pos + (size_t)bh * S_ * S_;
        #pragma unroll
        for (int mt = 0; mt < 2; mt++)
            #pragma unroll
            for (int nt = 0; nt < 4; nt++) {
                const int row = m0 + wm + (mt << 4) + g;
                const int col = n0 + wn + (nt << 3) + (t << 1);
                o[(size_t)row * S_ + col]           = acc[mt][nt][0];
                o[(size_t)row * S_ + col + 1]       = acc[mt][nt][1];
                o[(size_t)(row + 8) * S_ + col]     = acc[mt][nt][2];
                o[(size_t)(row + 8) * S_ + col + 1] = acc[mt][nt][3];
            }
    } else {
        const int mm = g_mask_mode;
        const float scale = 0.04419417382415922f;  // 1/sqrt(512)
        float* o = attnout + (size_t)bh * S_ * S_;
        const float* P = g_pos + (size_t)bh * S_ * S_;
        #pragma unroll
        for (int mt = 0; mt < 2; mt++)
            #pragma unroll
            for (int nt = 0; nt < 4; nt++)
                #pragma unroll
                for (int e = 0; e < 4; e++) {
                    const int q    = m0 + wm + (mt << 4) + g + ((e >> 1) << 3);
                    const int kcol = n0 + wn + (nt << 3) + (t << 1) + (e & 1);
                    float p;
                    if (kcol <= q)          p = P[(size_t)q * S_ + (kcol - q + S_ - 1)];
                    else if (kcol == q + 1) p = 0.0f;
                    else                    p = P[(size_t)(q + 1) * S_ + (kcol - q - 2)];
                    float sc = (acc[mt][nt][e] + p) * scale;
                    const size_t midx = (size_t)b * S_ * S_ + (size_t)q * S_ + kcol;
                    bool msk;
                    if (mm == 1)      msk = ((const int*)mask)[midx] != 0;
                    else if (mm == 2) msk = ((const float*)mask)[midx] != 0.0f;
                    else              msk = ((const unsigned char*)mask)[midx] != 0;
                    o[(size_t)q * S_ + kcol] = msk ? -10000.0f : sc;
                }
    }
}

// ---------------------------------------------------------------------------
// Row softmax over S=1024, one 256-thread block per row, in place.
// ---------------------------------------------------------------------------
__global__ void __launch_bounds__(256)
softmax_kernel(float* __restrict__ attn)
{
    const size_t row = blockIdx.x;
    float* p = attn + row * S_;
    const int tid = threadIdx.x;

    float v0 = p[tid], v1 = p[tid + 256], v2 = p[tid + 512], v3 = p[tid + 768];
    float mx = fmaxf(fmaxf(v0, v1), fmaxf(v2, v3));

    __shared__ float red[8];
    #pragma unroll
    for (int o = 16; o > 0; o >>= 1) mx = fmaxf(mx, __shfl_xor_sync(0xffffffffu, mx, o));
    if ((tid & 31) == 0) red[tid >> 5] = mx;
    __syncthreads();
    float m = fmaxf(fmaxf(fmaxf(red[0], red[1]), fmaxf(red[2], red[3])),
                    fmaxf(fmaxf(red[4], red[5]), fmaxf(red[6], red[7])));
    __syncthreads();

    v0 = __expf(v0 - m); v1 = __expf(v1 - m); v2 = __expf(v2 - m); v3 = __expf(v3 - m);
    float s = v0 + v1 + v2 + v3;
    #pragma unroll
    for (int o = 16; o > 0; o >>= 1) s += __shfl_xor_sync(0xffffffffu, s, o);
    if ((tid & 31) == 0) red[tid >> 5] = s;
    __syncthreads();
    float tot = red[0] + red[1] + red[2] + red[3] + red[4] + red[5] + red[6] + red[7];
    float inv = 1.0f / tot;

    p[tid]       = v0 * inv;
    p[tid + 256] = v1 * inv;
    p[tid + 512] = v2 * inv;
    p[tid + 768] = v3 * inv;
}

// ---------------------------------------------------------------------------
// Batched AV GEMM per (b,h): ctx[q, hd] = sum_k attn[q,k] * vh[k, hd]
// M=1024, N=64, K=1024. Block 128x64, BK=32, tf32 mma.
// Bs stored [k][n] (vh is k-major) so no transpose on load.
// ---------------------------------------------------------------------------
__global__ void __launch_bounds__(256)
av_tf32(const float* __restrict__ attn)
{
    __shared__ unsigned As[128][36];
    __shared__ unsigned Bs[32][72];
    const int bh = blockIdx.z, b = bh >> 3, h = bh & 7;
    const int tid  = threadIdx.x;
    const int warp = tid >> 5, lane = tid & 31;
    const int g = lane >> 2, t = lane & 3;
    const int wm = (warp >> 1) << 5, wn = (warp & 1) << 5;
    const int m0 = blockIdx.y << 7;

    const int ar = tid >> 1, ac = (tid & 1) << 4;
    const int vr = tid >> 3, vc = (tid & 7) << 3;

    float acc[2][4][4] = {};

    const float* Abase = attn + (size_t)bh * S_ * S_;

    for (int k0 = 0; k0 < S_; k0 += 32) {
        const float* Ap = Abase + (size_t)(m0 + ar) * S_ + k0 + ac;
        const float* Vp = g_vh + (size_t)((b << 10) + k0 + vr) * D_ + (h << 6) + vc;
        float4 a0 = *(const float4*)(Ap + 0);
        float4 a1 = *(const float4*)(Ap + 4);
        float4 a2 = *(const float4*)(Ap + 8);
        float4 a3 = *(const float4*)(Ap + 12);
        float4 v0 = *(const float4*)(Vp + 0);
        float4 v1 = *(const float4*)(Vp + 4);
        __syncthreads();
        *(uint4*)&As[ar][ac + 0]  = make_uint4(f2tf(a0.x), f2tf(a0.y), f2tf(a0.z), f2tf(a0.w));
        *(uint4*)&As[ar][ac + 4]  = make_uint4(f2tf(a1.x), f2tf(a1.y), f2tf(a1.z), f2tf(a1.w));
        *(uint4*)&As[ar][ac + 8]  = make_uint4(f2tf(a2.x), f2tf(a2.y), f2tf(a2.z), f2tf(a2.w));
        *(uint4*)&As[ar][ac + 12] = make_uint4(f2tf(a3.x), f2tf(a3.y), f2tf(a3.z), f2tf(a3.w));
        *(uint4*)&Bs[vr][vc + 0]  = make_uint4(f2tf(v0.x), f2tf(v0.y), f2tf(v0.z), f2tf(v0.w));
        *(uint4*)&Bs[vr][vc + 4]  = make_uint4(f2tf(v1.x), f2tf(v1.y), f2tf(v1.z), f2tf(v1.w));
        __syncthreads();
        #pragma unroll
        for (int kk = 0; kk < 4; kk++) {
            const int k8 = kk << 3;
            unsigned af[2][4], bf[4][2];
            #pragma unroll
            for (int mt = 0; mt < 2; mt++) {
                const int r = wm + (mt << 4) + g;
                af[mt][0] = As[r][k8 + t];
                af[mt][1] = As[r + 8][k8 + t];
                af[mt][2] = As[r][k8 + t + 4];
                af[mt][3] = As[r + 8][k8 + t + 4];
            }
            #pragma unroll
            for (int nt = 0; nt < 4; nt++) {
                const int c = wn + (nt << 3) + g;
                bf[nt][0] = Bs[k8 + t][c];
                bf[nt][1] = Bs[k8 + t + 4][c];
            }
            #pragma unroll
            for (int mt = 0; mt < 2; mt++)
                #pragma unroll
                for (int nt = 0; nt < 4; nt++)
                    mma8(acc[mt][nt], af[mt], bf[nt]);
        }
    }

    #pragma unroll
    for (int mt = 0; mt < 2; mt++)
        #pragma unroll
        for (int nt = 0; nt < 4; nt++) {
            const int q   = m0 + wm + (mt << 4) + g;
            const int col = (h << 6) + wn + (nt << 3) + (t << 1);
            g_ctx[(size_t)((b << 10) + q) * D_ + col]           = acc[mt][nt][0];
            g_ctx[(size_t)((b << 10) + q) * D_ + col + 1]       = acc[mt][nt][1];
            g_ctx[(size_t)((b << 10) + q + 8) * D_ + col]       = acc[mt][nt][2];
            g_ctx[(size_t)((b << 10) + q + 8) * D_ + col + 1]   = acc[mt][nt][3];
        }
}

// ---------------------------------------------------------------------------
// kernel_launch: graph-capturable pipeline, default stream, no allocations.
// Output layout: context [8,1024,512] then attn [8,8,1024,1024].
// ---------------------------------------------------------------------------
extern "C" void kernel_launch(void* const* d_in, const int* in_sizes, int n_in,
                              void* d_out, int out_size)
{
    const float* q    = (const float*)d_in[0];
    const float* k    = (const float*)d_in[1];
    const float* v    = (const float*)d_in[2];
    const float* pos  = (const float*)d_in[3];
    const void*  mask = d_in[4];
    const float* Wq   = (const float*)d_in[5];
    const float* bq   = (const float*)d_in[6];
    const float* Wk   = (const float*)d_in[7];
    const float* bk   = (const float*)d_in[8];
    const float* Wv   = (const float*)d_in[9];
    const float* bv   = (const float*)d_in[10];
    const float* Wpos = (const float*)d_in[11];
    const float* Wout = (const float*)d_in[12];
    const float* bout = (const float*)d_in[13];
    const float* u    = (const float*)d_in[14];
    const float* vb   = (const float*)d_in[15];

    float* out  = (float*)d_out;
    float* attn = out + (size_t)MT_ * D_;   // context first, then attn

    float *p_qh, *p_kh, *p_vh, *p_ph, *p_ctx;
    cudaGetSymbolAddress((void**)&p_qh,  g_qh);
    cudaGetSymbolAddress((void**)&p_kh,  g_kh);
    cudaGetSymbolAddress((void**)&p_vh,  g_vh);
    cudaGetSymbolAddress((void**)&p_ph,  g_ph);
    cudaGetSymbolAddress((void**)&p_ctx, g_ctx);

    detect_mask_kernel<<<1, 32>>>(mask);

    // Projections: x @ W^T + b  (tf32 tensor cores)
    dim3 gproj(D_ / 64, MT_ / 128);
    gemm_nt_tf32<<<gproj, 256>>>(q,   Wq,   bq,      p_qh);
    gemm_nt_tf32<<<gproj, 256>>>(k,   Wk,   bk,      p_kh);
    gemm_nt_tf32<<<gproj, 256>>>(v,   Wv,   bv,      p_vh);
    gemm_nt_tf32<<<gproj, 256>>>(pos, Wpos, nullptr, p_ph);

    // Raw positional scores: (qh + v_bias) . ph^T  -> g_pos
    dim3 gscore(S_ / 64, S_ / 128, BH_);
    score_tf32<0><<<gscore, 256>>>(p_ph, vb, mask, attn);

    // Content + shift + scale + mask -> pre-softmax scores into attn buffer
    score_tf32<1><<<gscore, 256>>>(p_kh, u, mask, attn);

    // Row softmax (in place)
    softmax_kernel<<<BH_ * S_, 256>>>(attn);

    // context heads = attn @ vh  (tf32)
    dim3 gav(1, S_ / 128, BH_);
    av_tf32<<<gav, 256>>>(attn);

    // Output projection: ctx @ Wout^T + bout -> d_out
    gemm_nt_tf32<<<gproj, 256>>>(p_ctx, Wout, bout, out);
}